// round 1
// baseline (speedup 1.0000x reference)
#include <cuda_runtime.h>
#include <math.h>

#define NCLS 20
#define NBINS 16
#define TOPK 9
#define MGT 32
#define TPB 256

// ---- device-global accumulators / scratch (no allocations allowed) ----
__device__ double g_acc[3];                  // qfl_sum, dfl_sum, giou_sum
__device__ unsigned long long g_poscnt;      // number of positive anchors
__device__ float g_thr[4096];                // ATSS threshold per (b,m)

__global__ void init_kernel() {
    g_acc[0] = 0.0; g_acc[1] = 0.0; g_acc[2] = 0.0;
    g_poscnt = 0ull;
}

// ---------------------------------------------------------------------------
// Kernel A: per (b,m) GT, find top-9 nearest anchors (by center distance),
// threshold = mean(iou) + std(iou, ddof=1) of those 9.
// One block per (b,m). 256 threads, per-thread sorted top-9, tree-merge in smem.
// ---------------------------------------------------------------------------
__global__ __launch_bounds__(TPB)
void thr_kernel(const float* __restrict__ anchors,
                const float* __restrict__ gt, int N) {
    int bm = blockIdx.x;
    float4 g = ((const float4*)gt)[bm];
    float gcx = 0.5f * (g.x + g.z), gcy = 0.5f * (g.y + g.w);
    float areab = (g.z - g.x) * (g.w - g.y);
    int tid = threadIdx.x;

    float d9[TOPK], i9[TOPK];
#pragma unroll
    for (int j = 0; j < TOPK; j++) { d9[j] = 3.4e38f; i9[j] = 0.f; }

    const float4* anc = (const float4*)anchors;
    for (int n = tid; n < N; n += TPB) {
        float4 a = anc[n];
        float acx = 0.5f * (a.x + a.z), acy = 0.5f * (a.y + a.w);
        float ddx = acx - gcx, ddy = acy - gcy;
        float dist = ddx * ddx + ddy * ddy;   // monotonic in ||.||, no sqrt needed
        if (dist < d9[TOPK - 1]) {
            float iw = fmaxf(fminf(a.z, g.z) - fmaxf(a.x, g.x), 0.f);
            float ih = fmaxf(fminf(a.w, g.w) - fmaxf(a.y, g.y), 0.f);
            float inter = iw * ih;
            float areaa = (a.z - a.x) * (a.w - a.y);
            float uni = areaa + areab - inter;
            float iou = inter / fmaxf(uni, 1e-9f);
            float cd = dist, ci = iou;
#pragma unroll
            for (int j = 0; j < TOPK; j++) {
                if (cd < d9[j]) {
                    float t = d9[j]; d9[j] = cd; cd = t;
                    t = i9[j]; i9[j] = ci; ci = t;
                }
            }
        }
    }

    __shared__ float sd[TPB * TOPK], si[TPB * TOPK];
#pragma unroll
    for (int j = 0; j < TOPK; j++) { sd[tid * TOPK + j] = d9[j]; si[tid * TOPK + j] = i9[j]; }
    __syncthreads();

    for (int off = TPB / 2; off >= 1; off >>= 1) {
        if (tid < off) {
            float od[TOPK], oi[TOPK];
            int p = 0, q = 0;
            float* Ad = &sd[tid * TOPK];          float* Ai = &si[tid * TOPK];
            float* Bd = &sd[(tid + off) * TOPK];  float* Bi = &si[(tid + off) * TOPK];
#pragma unroll
            for (int k = 0; k < TOPK; k++) {
                float da = Ad[p], db = Bd[q];
                bool ta = (da <= db);
                od[k] = ta ? da : db;
                oi[k] = ta ? Ai[p] : Bi[q];
                if (ta) p++; else q++;
            }
#pragma unroll
            for (int k = 0; k < TOPK; k++) { Ad[k] = od[k]; Ai[k] = oi[k]; }
        }
        __syncthreads();
    }

    if (tid == 0) {
        float s = 0.f;
#pragma unroll
        for (int k = 0; k < TOPK; k++) s += si[k];
        float mean = s / (float)TOPK;
        float v = 0.f;
#pragma unroll
        for (int k = 0; k < TOPK; k++) { float d = si[k] - mean; v += d * d; }
        float stdv = sqrtf(v / (float)(TOPK - 1));  // ddof=1
        g_thr[bm] = mean + stdv;
    }
}

// ---------------------------------------------------------------------------
// Kernel B: fused assignment + QFL + DFL + GIoU. One thread per (b,n).
// reg_preds only touched for positive anchors (kills 89MB of the 120MB input).
// ---------------------------------------------------------------------------
__global__ __launch_bounds__(TPB)
void loss_kernel(const float* __restrict__ cls_preds,
                 const float* __restrict__ reg_preds,
                 const float* __restrict__ anchors,
                 const float* __restrict__ gt,
                 const int* __restrict__ labels, int N) {
    __shared__ float sx1[MGT], sy1[MGT], sx2[MGT], sy2[MGT], sar[MGT], sth[MGT];
    __shared__ int slab[MGT];
    int b = blockIdx.y;
    int tid = threadIdx.x;
    if (tid < MGT) {
        float4 g = ((const float4*)gt)[b * MGT + tid];
        sx1[tid] = g.x; sy1[tid] = g.y; sx2[tid] = g.z; sy2[tid] = g.w;
        sar[tid] = (g.z - g.x) * (g.w - g.y);
        sth[tid] = g_thr[b * MGT + tid];
        slab[tid] = labels[b * MGT + tid];
    }
    __syncthreads();

    int n = blockIdx.x * TPB + tid;
    float qfl = 0.f;
    double dflv = 0.0;
    float giouv = 0.f;
    int posf = 0;

    if (n < N) {
        float4 a = ((const float4*)anchors)[n];
        float acx = 0.5f * (a.x + a.z), acy = 0.5f * (a.y + a.w);
        float areaa = (a.z - a.x) * (a.w - a.y);

        int matched = -1; float isel = 0.f;
#pragma unroll 8
        for (int m = 0; m < MGT; m++) {
            float iw = fmaxf(fminf(a.z, sx2[m]) - fmaxf(a.x, sx1[m]), 0.f);
            float ih = fmaxf(fminf(a.w, sy2[m]) - fmaxf(a.y, sy1[m]), 0.f);
            float inter = iw * ih;
            float iou = inter / fmaxf(areaa + sar[m] - inter, 1e-9f);
            bool inside = (acx >= sx1[m]) && (acx <= sx2[m]) &&
                          (acy >= sy1[m]) && (acy <= sy2[m]);
            if (inside && iou >= sth[m]) { matched = m; isel = iou; }
        }

        int cls_t = 0; float it = 0.f;
        float gx1 = 0.f, gy1 = 0.f, gx2 = 0.f, gy2 = 0.f;
        if (matched >= 0) {
            cls_t = slab[matched]; it = isel;
            gx1 = sx1[matched]; gy1 = sy1[matched];
            gx2 = sx2[matched]; gy2 = sy2[matched];
            posf = 1;
        }

        // ---- Quality Focal Loss (all anchors, all classes) ----
        const float4* cp = (const float4*)(cls_preds + ((size_t)b * N + n) * NCLS);
#pragma unroll
        for (int v = 0; v < NCLS / 4; v++) {
            float4 x4 = cp[v];
            float xs[4] = {x4.x, x4.y, x4.z, x4.w};
#pragma unroll
            for (int j = 0; j < 4; j++) {
                int c = v * 4 + j;
                float x = xs[j];
                float oh = (c == cls_t) ? 1.f : 0.f;
                float psig = 1.f / (1.f + __expf(-x));
                float pt = oh * psig + (1.f - oh) * (1.f - psig);
                float wq = it * (1.f - pt) + (1.f - it) * pt;
                wq *= wq;
                float bce = fmaxf(x, 0.f) - x * oh + log1pf(__expf(-fabsf(x)));
                qfl += wq * bce;
            }
        }

        // ---- DFL + GIoU (positive anchors only) ----
        if (posf) {
            const float* rp = reg_preds + ((size_t)b * N + n) * (4 * NBINS);
            float gb[4] = {gx1, gy1, gx2, gy2};
            float delta[4];
#pragma unroll
            for (int s = 0; s < 4; s++) {
                float l[NBINS];
                const float4* rp4 = (const float4*)(rp + s * NBINS);
#pragma unroll
                for (int v = 0; v < NBINS / 4; v++) {
                    float4 t = rp4[v];
                    l[v * 4 + 0] = t.x; l[v * 4 + 1] = t.y;
                    l[v * 4 + 2] = t.z; l[v * 4 + 3] = t.w;
                }
                float mx = l[0];
#pragma unroll
                for (int k = 1; k < NBINS; k++) mx = fmaxf(mx, l[k]);
                float se = 0.f, sek = 0.f;
#pragma unroll
                for (int k = 0; k < NBINS; k++) {
                    float e = __expf(l[k] - mx);
                    se += e; sek += e * (float)k;
                }
                float lse = __logf(se) + mx;
                delta[s] = sek / (se * (float)(NBINS - 1));

                float ts = gb[s] * (float)(NBINS - 1);
                int li = (int)ts;                       // trunc, ts >= 0
                li = max(0, min(li, NBINS - 2));
                float wr = ts - (float)li;
                float wl = 1.f - wr;
                float lpl = 0.f, lpr = 0.f;             // avoid dynamic reg indexing
#pragma unroll
                for (int k = 0; k < NBINS; k++) {
                    if (k == li)     lpl = l[k];
                    if (k == li + 1) lpr = l[k];
                }
                lpl -= lse; lpr -= lse;
                dflv += (double)(-(wl * lpl + wr * lpr));
            }
            // delta2bbox + elementwise GIoU vs matched GT
            float w = a.z - a.x, h = a.w - a.y;
            float cx = a.x + 0.5f * w, cy = a.y + 0.5f * h;
            float pcx = delta[0] * w + cx, pcy = delta[1] * h + cy;
            float pw = __expf(delta[2]) * w, ph = __expf(delta[3]) * h;
            float px1 = pcx - 0.5f * pw, py1 = pcy - 0.5f * ph;
            float px2 = pcx + 0.5f * pw, py2 = pcy + 0.5f * ph;

            float iw = fmaxf(fminf(px2, gx2) - fmaxf(px1, gx1), 0.f);
            float ih = fmaxf(fminf(py2, gy2) - fmaxf(py1, gy1), 0.f);
            float inter = iw * ih;
            float aa = (px2 - px1) * (py2 - py1);
            float ab = (gx2 - gx1) * (gy2 - gy1);
            float uni = aa + ab - inter;
            float iou = inter / fmaxf(uni, 1e-9f);
            float ew = fmaxf(fmaxf(px2, gx2) - fminf(px1, gx1), 0.f);
            float eh = fmaxf(fmaxf(py2, gy2) - fminf(py1, gy1), 0.f);
            float enc = ew * eh;
            float giou = iou - (enc - uni) / fmaxf(enc, 1e-9f);
            giouv = 1.f - giou;
        }
    }

    // ---- block reduction (doubles), then atomic into globals ----
    double dq = (double)qfl, dd = dflv, dg = (double)giouv;
    int pc = posf;
#pragma unroll
    for (int o = 16; o >= 1; o >>= 1) {
        dq += __shfl_down_sync(0xffffffffu, dq, o);
        dd += __shfl_down_sync(0xffffffffu, dd, o);
        dg += __shfl_down_sync(0xffffffffu, dg, o);
        pc += __shfl_down_sync(0xffffffffu, pc, o);
    }
    __shared__ double rq[TPB / 32], rd[TPB / 32], rg[TPB / 32];
    __shared__ int rc[TPB / 32];
    int wid = tid >> 5, lane = tid & 31;
    if (lane == 0) { rq[wid] = dq; rd[wid] = dd; rg[wid] = dg; rc[wid] = pc; }
    __syncthreads();
    if (tid == 0) {
        double tq = 0, td = 0, tg = 0; int tc = 0;
        for (int i = 0; i < TPB / 32; i++) { tq += rq[i]; td += rd[i]; tg += rg[i]; tc += rc[i]; }
        atomicAdd(&g_acc[0], tq);
        atomicAdd(&g_acc[1], td);
        atomicAdd(&g_acc[2], tg);
        atomicAdd(&g_poscnt, (unsigned long long)tc);
    }
}

__global__ void finalize_kernel(float* out) {
    unsigned long long cnt = g_poscnt;
    double np  = (double)(cnt > 0 ? cnt : 1ull);         // num_pos_cls == num_pos here (labels >= 1)
    double npd = (double)(cnt > 0 ? cnt * 4ull : 1ull);
    double qfl = g_acc[0] / np;
    double dfl = g_acc[1] / npd;
    dfl = fmin(fmax(dfl, 0.0), 1.0);
    double gi = g_acc[2] / np;
    out[0] = (float)(qfl + dfl + gi);   // total (GIOU_WEIGHT = 1)
    out[1] = (float)qfl;
    out[2] = (float)dfl;
    out[3] = (float)gi;
}

extern "C" void kernel_launch(void* const* d_in, const int* in_sizes, int n_in,
                              void* d_out, int out_size) {
    const float* cls_preds = (const float*)d_in[0];
    const float* reg_preds = (const float*)d_in[1];
    const float* anchors   = (const float*)d_in[2];
    const float* gt        = (const float*)d_in[3];
    const int*   labels    = (const int*)d_in[4];

    int N = in_sizes[2] / 4;                 // 21824
    int B = in_sizes[3] / (MGT * 4);         // 16

    init_kernel<<<1, 1>>>();
    thr_kernel<<<B * MGT, TPB>>>(anchors, gt, N);
    dim3 grid((N + TPB - 1) / TPB, B);
    loss_kernel<<<grid, TPB>>>(cls_preds, reg_preds, anchors, gt, labels, N);
    finalize_kernel<<<1, 1>>>((float*)d_out);
}

// round 2
// speedup vs baseline: 1.8389x; 1.8389x over previous
#include <cuda_runtime.h>
#include <math.h>

#define NCLS 20
#define NBINS 16
#define TOPK 9
#define MGT 32
#define TPB 256

// ---- device-global accumulators / scratch ----
__device__ double g_acc[3];                  // qfl_sum, dfl_sum, giou_sum
__device__ unsigned long long g_poscnt;
__device__ unsigned int g_cnt;               // last-block counter
__device__ float g_thr[4096];                // ATSS threshold per (b,m)

// ---------------------------------------------------------------------------
// Kernel A: analytic ATSS threshold. One WARP per (b,m) GT.
// Candidate superset: per level, 11x11 (or n x n if n<11) window of grid cells
// around the nearest cell to the GT center. Guaranteed to contain the global
// top-9 by center distance. 548 candidates total vs 21824 anchors.
// ---------------------------------------------------------------------------
__global__ __launch_bounds__(32)
void thr_kernel(const float* __restrict__ gt) {
    // fold accumulator reset into this kernel (loss launches after, stream-ordered)
    if (blockIdx.x == 0 && threadIdx.x == 0) {
        g_acc[0] = 0.0; g_acc[1] = 0.0; g_acc[2] = 0.0;
        g_poscnt = 0ull; g_cnt = 0u;
    }

    const float SF[5]   = {8.f, 16.f, 32.f, 64.f, 128.f};
    const int   NL[5]   = {128, 64, 32, 16, 8};
    const int   AOFF[5] = {0, 16384, 20480, 21504, 21760};
    const int   W[5]    = {11, 11, 11, 11, 8};
    const int   CB[5]   = {0, 121, 242, 363, 484};
    const int   CTOT    = 548;

    int bm = blockIdx.x;
    float4 g = ((const float4*)gt)[bm];
    float gcx = 0.5f * (g.x + g.z), gcy = 0.5f * (g.y + g.w);
    float areab = (g.z - g.x) * (g.w - g.y);
    int lane = threadIdx.x;

    // per-level window origins
    int lox[5], loy[5];
#pragma unroll
    for (int l = 0; l < 5; l++) {
        float s = SF[l]; int n = NL[l]; int w = W[l];
        int ixs = (int)floorf(gcx / s); ixs = min(max(ixs, 0), n - 1);
        int iys = (int)floorf(gcy / s); iys = min(max(iys, 0), n - 1);
        lox[l] = min(max(ixs - 5, 0), n - w);
        loy[l] = min(max(iys - 5, 0), n - w);
    }

    float d9[TOPK], i9[TOPK]; int x9[TOPK];
#pragma unroll
    for (int j = 0; j < TOPK; j++) { d9[j] = 3.4e38f; i9[j] = 0.f; x9[j] = 0x7fffffff; }

    for (int c = lane; c < CTOT; c += 32) {
        int l = (c < 121) ? 0 : (c < 242) ? 1 : (c < 363) ? 2 : (c < 484) ? 3 : 4;
        int local = c - CB[l];
        int w = W[l], n = NL[l];
        int jx = local % w, jy = local / w;
        int ix = lox[l] + jx, iy = loy[l] + jy;
        float s = SF[l];
        float cx = (ix + 0.5f) * s, cy = (iy + 0.5f) * s;
        float hh = 2.f * s;
        float ax1 = cx - hh, ay1 = cy - hh, ax2 = cx + hh, ay2 = cy + hh;
        float ddx = cx - gcx, ddy = cy - gcy;
        float dist = ddx * ddx + ddy * ddy;   // monotone in norm
        float iw = fmaxf(fminf(ax2, g.z) - fmaxf(ax1, g.x), 0.f);
        float ih = fmaxf(fminf(ay2, g.w) - fmaxf(ay1, g.y), 0.f);
        float inter = iw * ih;
        float areaa = (ax2 - ax1) * (ay2 - ay1);
        float iou = inter / fmaxf(areaa + areab - inter, 1e-9f);
        int idx = AOFF[l] + iy * n + ix;

        bool lt = (dist < d9[TOPK - 1]) ||
                  (dist == d9[TOPK - 1] && idx < x9[TOPK - 1]);
        if (lt) {
            float cd = dist, ci = iou; int cxi = idx;
#pragma unroll
            for (int j = 0; j < TOPK; j++) {
                bool sw = (cd < d9[j]) || (cd == d9[j] && cxi < x9[j]);
                if (sw) {
                    float t = d9[j]; d9[j] = cd; cd = t;
                    t = i9[j]; i9[j] = ci; ci = t;
                    int ti = x9[j]; x9[j] = cxi; cxi = ti;
                }
            }
        }
    }

    // warp merge via smem (dynamic-index merge must be in smem, not regs)
    __shared__ float sd[32 * TOPK], si[32 * TOPK];
    __shared__ int   sx[32 * TOPK];
#pragma unroll
    for (int j = 0; j < TOPK; j++) {
        sd[lane * TOPK + j] = d9[j];
        si[lane * TOPK + j] = i9[j];
        sx[lane * TOPK + j] = x9[j];
    }
    __syncwarp();

    for (int off = 16; off >= 1; off >>= 1) {
        if (lane < off) {
            float od[TOPK], oi[TOPK]; int ox[TOPK];
            int pa = lane * TOPK, pb = (lane + off) * TOPK;
            int p = 0, q = 0;
#pragma unroll
            for (int k = 0; k < TOPK; k++) {
                float da = sd[pa + p], db = sd[pb + q];
                int ia = sx[pa + p], ib = sx[pb + q];
                bool ta = (da < db) || (da == db && ia <= ib);
                od[k] = ta ? da : db;
                oi[k] = ta ? si[pa + p] : si[pb + q];
                ox[k] = ta ? ia : ib;
                if (ta) p++; else q++;
            }
#pragma unroll
            for (int k = 0; k < TOPK; k++) {
                sd[pa + k] = od[k]; si[pa + k] = oi[k]; sx[pa + k] = ox[k];
            }
        }
        __syncwarp();
    }

    if (lane == 0) {
        float s = 0.f;
#pragma unroll
        for (int k = 0; k < TOPK; k++) s += si[k];
        float mean = s / (float)TOPK;
        float v = 0.f;
#pragma unroll
        for (int k = 0; k < TOPK; k++) { float d = si[k] - mean; v += d * d; }
        float stdv = sqrtf(v / (float)(TOPK - 1));  // ddof=1
        g_thr[bm] = mean + stdv;
    }
}

// ---------------------------------------------------------------------------
// Kernel B: fused assignment + QFL + DFL + GIoU + last-block finalize.
// ---------------------------------------------------------------------------
__global__ __launch_bounds__(TPB)
void loss_kernel(const float* __restrict__ cls_preds,
                 const float* __restrict__ reg_preds,
                 const float* __restrict__ anchors,
                 const float* __restrict__ gt,
                 const int* __restrict__ labels, int N, float* __restrict__ out) {
    __shared__ float sx1[MGT], sy1[MGT], sx2[MGT], sy2[MGT], sar[MGT], sth[MGT];
    __shared__ int slab[MGT];
    int b = blockIdx.y;
    int tid = threadIdx.x;
    if (tid < MGT) {
        float4 g = ((const float4*)gt)[b * MGT + tid];
        sx1[tid] = g.x; sy1[tid] = g.y; sx2[tid] = g.z; sy2[tid] = g.w;
        sar[tid] = (g.z - g.x) * (g.w - g.y);
        sth[tid] = g_thr[b * MGT + tid];
        slab[tid] = labels[b * MGT + tid];
    }
    __syncthreads();

    int n = blockIdx.x * TPB + tid;
    float qfl = 0.f;
    double dflv = 0.0;
    float giouv = 0.f;
    int posf = 0;

    if (n < N) {
        float4 a = ((const float4*)anchors)[n];
        float acx = 0.5f * (a.x + a.z), acy = 0.5f * (a.y + a.w);
        float areaa = (a.z - a.x) * (a.w - a.y);

        int matched = -1; float isel = 0.f;
#pragma unroll 8
        for (int m = 0; m < MGT; m++) {
            float iw = fmaxf(fminf(a.z, sx2[m]) - fmaxf(a.x, sx1[m]), 0.f);
            float ih = fmaxf(fminf(a.w, sy2[m]) - fmaxf(a.y, sy1[m]), 0.f);
            float inter = iw * ih;
            float iou = inter / fmaxf(areaa + sar[m] - inter, 1e-9f);
            bool inside = (acx >= sx1[m]) && (acx <= sx2[m]) &&
                          (acy >= sy1[m]) && (acy <= sy2[m]);
            if (inside && iou >= sth[m]) { matched = m; isel = iou; }
        }

        int cls_t = 0; float it = 0.f;
        float gx1 = 0.f, gy1 = 0.f, gx2 = 0.f, gy2 = 0.f;
        if (matched >= 0) {
            cls_t = slab[matched]; it = isel;
            gx1 = sx1[matched]; gy1 = sy1[matched];
            gx2 = sx2[matched]; gy2 = sy2[matched];
            posf = 1;
        }

        // ---- Quality Focal Loss: 3 MUFU per element (EX2, RCP, LG2) ----
        const float4* cp = (const float4*)(cls_preds + ((size_t)b * N + n) * NCLS);
#pragma unroll
        for (int v = 0; v < NCLS / 4; v++) {
            float4 x4 = cp[v];
            float xs[4] = {x4.x, x4.y, x4.z, x4.w};
#pragma unroll
            for (int j = 0; j < 4; j++) {
                int c = v * 4 + j;
                float x = xs[j];
                bool is_t = (c == cls_t);
                float t = __expf(-fabsf(x));
                float r = __fdividef(1.f, 1.f + t);   // 1/(1+t)
                float L = -__logf(r);                 // log(1+t) = log1p(e^-|x|)
                float sgm  = (x >= 0.f) ? r : t * r;  // sigmoid(x), no cancellation
                float comp = (x >= 0.f) ? t * r : r;  // 1 - sigmoid(x)
                float pt = is_t ? sgm : comp;
                float w = fmaf(it, 1.f - 2.f * pt, pt);   // it*(1-pt)+(1-it)*pt
                w *= w;
                float oh = is_t ? 1.f : 0.f;
                float bce = fmaxf(x, 0.f) - x * oh + L;
                qfl += w * bce;
            }
        }

        // ---- DFL + GIoU (positive anchors only) ----
        if (posf) {
            const float* rp = reg_preds + ((size_t)b * N + n) * (4 * NBINS);
            float gb[4] = {gx1, gy1, gx2, gy2};
            float delta[4];
#pragma unroll
            for (int s = 0; s < 4; s++) {
                float l[NBINS];
                const float4* rp4 = (const float4*)(rp + s * NBINS);
#pragma unroll
                for (int v = 0; v < NBINS / 4; v++) {
                    float4 t = rp4[v];
                    l[v * 4 + 0] = t.x; l[v * 4 + 1] = t.y;
                    l[v * 4 + 2] = t.z; l[v * 4 + 3] = t.w;
                }
                float mx = l[0];
#pragma unroll
                for (int k = 1; k < NBINS; k++) mx = fmaxf(mx, l[k]);
                float se = 0.f, sek = 0.f;
#pragma unroll
                for (int k = 0; k < NBINS; k++) {
                    float e = __expf(l[k] - mx);
                    se += e; sek += e * (float)k;
                }
                float lse = __logf(se) + mx;
                delta[s] = sek / (se * (float)(NBINS - 1));

                float ts = gb[s] * (float)(NBINS - 1);
                int li = (int)ts;
                li = max(0, min(li, NBINS - 2));
                float wr = ts - (float)li;
                float wl = 1.f - wr;
                float lpl = 0.f, lpr = 0.f;
#pragma unroll
                for (int k = 0; k < NBINS; k++) {
                    if (k == li)     lpl = l[k];
                    if (k == li + 1) lpr = l[k];
                }
                lpl -= lse; lpr -= lse;
                dflv += (double)(-(wl * lpl + wr * lpr));
            }
            float w = a.z - a.x, h = a.w - a.y;
            float cx = a.x + 0.5f * w, cy = a.y + 0.5f * h;
            float pcx = delta[0] * w + cx, pcy = delta[1] * h + cy;
            float pw = __expf(delta[2]) * w, ph = __expf(delta[3]) * h;
            float px1 = pcx - 0.5f * pw, py1 = pcy - 0.5f * ph;
            float px2 = pcx + 0.5f * pw, py2 = pcy + 0.5f * ph;

            float iw = fmaxf(fminf(px2, gx2) - fmaxf(px1, gx1), 0.f);
            float ih = fmaxf(fminf(py2, gy2) - fmaxf(py1, gy1), 0.f);
            float inter = iw * ih;
            float aa = (px2 - px1) * (py2 - py1);
            float ab = (gx2 - gx1) * (gy2 - gy1);
            float uni = aa + ab - inter;
            float iou = inter / fmaxf(uni, 1e-9f);
            float ew = fmaxf(fmaxf(px2, gx2) - fminf(px1, gx1), 0.f);
            float eh = fmaxf(fmaxf(py2, gy2) - fminf(py1, gy1), 0.f);
            float enc = ew * eh;
            float giou = iou - (enc - uni) / fmaxf(enc, 1e-9f);
            giouv = 1.f - giou;
        }
    }

    // ---- block reduction (doubles), then atomic into globals ----
    double dq = (double)qfl, dd = dflv, dg = (double)giouv;
    int pc = posf;
#pragma unroll
    for (int o = 16; o >= 1; o >>= 1) {
        dq += __shfl_down_sync(0xffffffffu, dq, o);
        dd += __shfl_down_sync(0xffffffffu, dd, o);
        dg += __shfl_down_sync(0xffffffffu, dg, o);
        pc += __shfl_down_sync(0xffffffffu, pc, o);
    }
    __shared__ double rq[TPB / 32], rd[TPB / 32], rg[TPB / 32];
    __shared__ int rc[TPB / 32];
    int wid = tid >> 5, lane = tid & 31;
    if (lane == 0) { rq[wid] = dq; rd[wid] = dd; rg[wid] = dg; rc[wid] = pc; }
    __syncthreads();
    if (tid == 0) {
        double tq = 0, td = 0, tg = 0; int tc = 0;
        for (int i = 0; i < TPB / 32; i++) { tq += rq[i]; td += rd[i]; tg += rg[i]; tc += rc[i]; }
        atomicAdd(&g_acc[0], tq);
        atomicAdd(&g_acc[1], td);
        atomicAdd(&g_acc[2], tg);
        atomicAdd(&g_poscnt, (unsigned long long)tc);
        __threadfence();
        unsigned int total = gridDim.x * gridDim.y;
        unsigned int done = atomicAdd(&g_cnt, 1u);
        if (done == total - 1) {
            // last block: finalize (atomicAdd(.,0) for coherent read)
            double sq = atomicAdd(&g_acc[0], 0.0);
            double sd2 = atomicAdd(&g_acc[1], 0.0);
            double sg = atomicAdd(&g_acc[2], 0.0);
            unsigned long long cnt = atomicAdd(&g_poscnt, 0ull);
            double np  = (double)(cnt > 0 ? cnt : 1ull);
            double npd = (double)(cnt > 0 ? cnt * 4ull : 1ull);
            double qv = sq / np;
            double dv = sd2 / npd;
            dv = fmin(fmax(dv, 0.0), 1.0);
            double gv = sg / np;
            out[0] = (float)(qv + dv + gv);
            out[1] = (float)qv;
            out[2] = (float)dv;
            out[3] = (float)gv;
        }
    }
}

extern "C" void kernel_launch(void* const* d_in, const int* in_sizes, int n_in,
                              void* d_out, int out_size) {
    const float* cls_preds = (const float*)d_in[0];
    const float* reg_preds = (const float*)d_in[1];
    const float* anchors   = (const float*)d_in[2];
    const float* gt        = (const float*)d_in[3];
    const int*   labels    = (const int*)d_in[4];

    int N = in_sizes[2] / 4;                 // 21824
    int B = in_sizes[3] / (MGT * 4);         // 16

    thr_kernel<<<B * MGT, 32>>>(gt);
    dim3 grid((N + TPB - 1) / TPB, B);
    loss_kernel<<<grid, TPB>>>(cls_preds, reg_preds, anchors, gt, labels, N, (float*)d_out);
}

// round 3
// speedup vs baseline: 2.6806x; 1.4578x over previous
#include <cuda_runtime.h>
#include <math.h>

#define NCLS 20
#define NBINS 16
#define TOPK 9
#define MGT 32
#define TPB 256
#define NANCH 21824
#define BMAX 16

// ---- device-global accumulators / scratch ----
__device__ double g_acc[3];
__device__ unsigned long long g_poscnt;
__device__ unsigned int g_cnt;
__device__ float g_thr[4096];
__device__ unsigned int g_mask[BMAX * NANCH];   // bit m set => anchor center inside GT m

// ---------------------------------------------------------------------------
// Kernel A: analytic ATSS threshold (one warp per (b,m)) + zero g_mask + reset.
// ---------------------------------------------------------------------------
__global__ __launch_bounds__(32)
void thr_kernel(const float* __restrict__ gt, int B) {
    // zero the candidate mask (grid-stride across all warps)
    {
        int nwords = B * NANCH;
        int gtid = blockIdx.x * 32 + threadIdx.x;
        int stride = gridDim.x * 32;
        for (int i = gtid; i < nwords; i += stride) g_mask[i] = 0u;
    }
    if (blockIdx.x == 0 && threadIdx.x == 0) {
        g_acc[0] = 0.0; g_acc[1] = 0.0; g_acc[2] = 0.0;
        g_poscnt = 0ull; g_cnt = 0u;
    }

    const float SF[5]   = {8.f, 16.f, 32.f, 64.f, 128.f};
    const int   NL[5]   = {128, 64, 32, 16, 8};
    const int   AOFF[5] = {0, 16384, 20480, 21504, 21760};
    const int   W[5]    = {11, 11, 11, 11, 8};
    const int   CB[5]   = {0, 121, 242, 363, 484};
    const int   CTOT    = 548;

    int bm = blockIdx.x;
    float4 g = ((const float4*)gt)[bm];
    float gcx = 0.5f * (g.x + g.z), gcy = 0.5f * (g.y + g.w);
    float areab = (g.z - g.x) * (g.w - g.y);
    int lane = threadIdx.x;

    int lox[5], loy[5];
#pragma unroll
    for (int l = 0; l < 5; l++) {
        float s = SF[l]; int n = NL[l]; int w = W[l];
        int ixs = (int)floorf(gcx / s); ixs = min(max(ixs, 0), n - 1);
        int iys = (int)floorf(gcy / s); iys = min(max(iys, 0), n - 1);
        lox[l] = min(max(ixs - 5, 0), n - w);
        loy[l] = min(max(iys - 5, 0), n - w);
    }

    float d9[TOPK], i9[TOPK]; int x9[TOPK];
#pragma unroll
    for (int j = 0; j < TOPK; j++) { d9[j] = 3.4e38f; i9[j] = 0.f; x9[j] = 0x7fffffff; }

    for (int c = lane; c < CTOT; c += 32) {
        int l = (c < 121) ? 0 : (c < 242) ? 1 : (c < 363) ? 2 : (c < 484) ? 3 : 4;
        int local = c - CB[l];
        int w = W[l], n = NL[l];
        int jx = local % w, jy = local / w;
        int ix = lox[l] + jx, iy = loy[l] + jy;
        float s = SF[l];
        float cx = (ix + 0.5f) * s, cy = (iy + 0.5f) * s;
        float hh = 2.f * s;
        float ax1 = cx - hh, ay1 = cy - hh, ax2 = cx + hh, ay2 = cy + hh;
        float ddx = cx - gcx, ddy = cy - gcy;
        float dist = ddx * ddx + ddy * ddy;
        float iw = fmaxf(fminf(ax2, g.z) - fmaxf(ax1, g.x), 0.f);
        float ih = fmaxf(fminf(ay2, g.w) - fmaxf(ay1, g.y), 0.f);
        float inter = iw * ih;
        float areaa = (ax2 - ax1) * (ay2 - ay1);
        float iou = inter / fmaxf(areaa + areab - inter, 1e-9f);
        int idx = AOFF[l] + iy * n + ix;

        bool lt = (dist < d9[TOPK - 1]) ||
                  (dist == d9[TOPK - 1] && idx < x9[TOPK - 1]);
        if (lt) {
            float cd = dist, ci = iou; int cxi = idx;
#pragma unroll
            for (int j = 0; j < TOPK; j++) {
                bool sw = (cd < d9[j]) || (cd == d9[j] && cxi < x9[j]);
                if (sw) {
                    float t = d9[j]; d9[j] = cd; cd = t;
                    t = i9[j]; i9[j] = ci; ci = t;
                    int ti = x9[j]; x9[j] = cxi; cxi = ti;
                }
            }
        }
    }

    __shared__ float sd[32 * TOPK], si[32 * TOPK];
    __shared__ int   sx[32 * TOPK];
#pragma unroll
    for (int j = 0; j < TOPK; j++) {
        sd[lane * TOPK + j] = d9[j];
        si[lane * TOPK + j] = i9[j];
        sx[lane * TOPK + j] = x9[j];
    }
    __syncwarp();

    for (int off = 16; off >= 1; off >>= 1) {
        if (lane < off) {
            float od[TOPK], oi[TOPK]; int ox[TOPK];
            int pa = lane * TOPK, pb = (lane + off) * TOPK;
            int p = 0, q = 0;
#pragma unroll
            for (int k = 0; k < TOPK; k++) {
                float da = sd[pa + p], db = sd[pb + q];
                int ia = sx[pa + p], ib = sx[pb + q];
                bool ta = (da < db) || (da == db && ia <= ib);
                od[k] = ta ? da : db;
                oi[k] = ta ? si[pa + p] : si[pb + q];
                ox[k] = ta ? ia : ib;
                if (ta) p++; else q++;
            }
#pragma unroll
            for (int k = 0; k < TOPK; k++) {
                sd[pa + k] = od[k]; si[pa + k] = oi[k]; sx[pa + k] = ox[k];
            }
        }
        __syncwarp();
    }

    if (lane == 0) {
        float s = 0.f;
#pragma unroll
        for (int k = 0; k < TOPK; k++) s += si[k];
        float mean = s / (float)TOPK;
        float v = 0.f;
#pragma unroll
        for (int k = 0; k < TOPK; k++) { float d = si[k] - mean; v += d * d; }
        float stdv = sqrtf(v / (float)(TOPK - 1));
        g_thr[bm] = mean + stdv;
    }
}

// ---------------------------------------------------------------------------
// Kernel A2: build candidate mask. One warp per (b,m). Per level, enumerate the
// (conservative) rectangle of cells whose centers may lie inside the GT box,
// re-test exact float condition, atomicOr bit m.
// ---------------------------------------------------------------------------
__global__ __launch_bounds__(32)
void mask_kernel(const float* __restrict__ gt) {
    const float SF[5]   = {8.f, 16.f, 32.f, 64.f, 128.f};
    const int   NL[5]   = {128, 64, 32, 16, 8};
    const int   AOFF[5] = {0, 16384, 20480, 21504, 21760};

    int bm = blockIdx.x;
    int b = bm / MGT, m = bm % MGT;
    float4 g = ((const float4*)gt)[bm];
    int lane = threadIdx.x;
    unsigned int bit = 1u << m;
    unsigned int* mk = g_mask + (size_t)b * NANCH;

#pragma unroll
    for (int l = 0; l < 5; l++) {
        float s = SF[l]; int n = NL[l];
        float inv = 1.f / s;
        int ix0 = max(0, (int)floorf(g.x * inv - 0.5f) - 1);
        int ix1 = min(n - 1, (int)ceilf(g.z * inv - 0.5f) + 1);
        int iy0 = max(0, (int)floorf(g.y * inv - 0.5f) - 1);
        int iy1 = min(n - 1, (int)ceilf(g.w * inv - 0.5f) + 1);
        int nx = ix1 - ix0 + 1, ny = iy1 - iy0 + 1;
        if (nx <= 0 || ny <= 0) continue;
        int cells = nx * ny;
        for (int c = lane; c < cells; c += 32) {
            int ix = ix0 + c % nx, iy = iy0 + c / nx;
            float cx = (ix + 0.5f) * s, cy = (iy + 0.5f) * s;
            if (cx >= g.x && cx <= g.z && cy >= g.y && cy <= g.w)
                atomicOr(&mk[AOFF[l] + iy * n + ix], bit);
        }
    }
}

// ---------------------------------------------------------------------------
// Kernel B: fused assignment + QFL + DFL + GIoU + last-block finalize.
// ---------------------------------------------------------------------------
__global__ __launch_bounds__(TPB)
void loss_kernel(const float* __restrict__ cls_preds,
                 const float* __restrict__ reg_preds,
                 const float* __restrict__ anchors,
                 const float* __restrict__ gt,
                 const int* __restrict__ labels, int N, float* __restrict__ out) {
    __shared__ float sx1[MGT], sy1[MGT], sx2[MGT], sy2[MGT], sar[MGT], sth[MGT];
    __shared__ int slab[MGT];
    int b = blockIdx.y;
    int tid = threadIdx.x;
    if (tid < MGT) {
        float4 g = ((const float4*)gt)[b * MGT + tid];
        sx1[tid] = g.x; sy1[tid] = g.y; sx2[tid] = g.z; sy2[tid] = g.w;
        sar[tid] = (g.z - g.x) * (g.w - g.y);
        sth[tid] = g_thr[b * MGT + tid];
        slab[tid] = labels[b * MGT + tid];
    }
    __syncthreads();

    int n = blockIdx.x * TPB + tid;
    float qfl = 0.f;
    double dflv = 0.0;
    float giouv = 0.f;
    int posf = 0;

    if (n < N) {
        // ---- bitmask matching: one LDG, usually zero ----
        unsigned int mask = g_mask[(size_t)b * N + n];
        int matched = -1; float isel = 0.f;
        float4 a;
        if (mask) {
            a = ((const float4*)anchors)[n];
            float areaa = (a.z - a.x) * (a.w - a.y);
            unsigned int mm = mask;
            while (mm) {
                int m = 31 - __clz(mm);
                mm &= ~(1u << m);
                float iw = fmaxf(fminf(a.z, sx2[m]) - fmaxf(a.x, sx1[m]), 0.f);
                float ih = fmaxf(fminf(a.w, sy2[m]) - fmaxf(a.y, sy1[m]), 0.f);
                float inter = iw * ih;
                float uni = fmaxf(areaa + sar[m] - inter, 1e-9f);
                if (inter >= sth[m] * uni) {          // iou >= thr, division-free
                    matched = m;
                    isel = inter / uni;               // one division, matched only
                    break;                            // highest m wins
                }
            }
        }

        int cls_t = 0; float it = 0.f;
        if (matched >= 0) { cls_t = slab[matched]; it = isel; posf = 1; }

        // ---- QFL: all classes as negatives (select-free), then correct target ----
        const float* cpf = cls_preds + ((size_t)b * N + n) * NCLS;
        const float4* cp4 = (const float4*)cpf;
#pragma unroll
        for (int v = 0; v < NCLS / 4; v++) {
            float4 x4 = cp4[v];
            float xs[4] = {x4.x, x4.y, x4.z, x4.w};
#pragma unroll
            for (int j = 0; j < 4; j++) {
                float u = __expf(xs[j]);
                float pn = __fdividef(1.f, 1.f + u);       // 1 - sigmoid(x)
                float L = -__logf(pn);                      // softplus(x) = bce(oh=0)
                float w = fmaf(it, fmaf(-2.f, pn, 1.f), pn);
                qfl = fmaf(w * w, L, qfl);
            }
        }
        {   // correction for the one-hot target class (class 0 when unmatched)
            float xt = cpf[cls_t];
            float u = __expf(xt);
            float pn = __fdividef(1.f, 1.f + u);
            float ps = u * pn;                               // sigmoid(xt)
            float Lneg = -__logf(pn);
            float wn = fmaf(it, fmaf(-2.f, pn, 1.f), pn);
            float un = __expf(-xt);
            float Lpos = __logf(1.f + un);                   // softplus(-xt) = bce(oh=1)
            float wp = fmaf(it, fmaf(-2.f, ps, 1.f), ps);
            qfl += wp * wp * Lpos - wn * wn * Lneg;
        }

        // ---- DFL + GIoU (positive anchors only) ----
        if (posf) {
            float gx1 = sx1[matched], gy1 = sy1[matched];
            float gx2 = sx2[matched], gy2 = sy2[matched];
            const float* rp = reg_preds + ((size_t)b * N + n) * (4 * NBINS);
            float gb[4] = {gx1, gy1, gx2, gy2};
            float delta[4];
#pragma unroll
            for (int s = 0; s < 4; s++) {
                float l[NBINS];
                const float4* rp4 = (const float4*)(rp + s * NBINS);
#pragma unroll
                for (int v = 0; v < NBINS / 4; v++) {
                    float4 t = rp4[v];
                    l[v * 4 + 0] = t.x; l[v * 4 + 1] = t.y;
                    l[v * 4 + 2] = t.z; l[v * 4 + 3] = t.w;
                }
                float mx = l[0];
#pragma unroll
                for (int k = 1; k < NBINS; k++) mx = fmaxf(mx, l[k]);
                float se = 0.f, sek = 0.f;
#pragma unroll
                for (int k = 0; k < NBINS; k++) {
                    float e = __expf(l[k] - mx);
                    se += e; sek += e * (float)k;
                }
                float lse = __logf(se) + mx;
                delta[s] = sek / (se * (float)(NBINS - 1));

                float ts = gb[s] * (float)(NBINS - 1);
                int li = (int)ts;
                li = max(0, min(li, NBINS - 2));
                float wr = ts - (float)li;
                float wl = 1.f - wr;
                float lpl = 0.f, lpr = 0.f;
#pragma unroll
                for (int k = 0; k < NBINS; k++) {
                    if (k == li)     lpl = l[k];
                    if (k == li + 1) lpr = l[k];
                }
                lpl -= lse; lpr -= lse;
                dflv += (double)(-(wl * lpl + wr * lpr));
            }
            float w = a.z - a.x, h = a.w - a.y;
            float cx = a.x + 0.5f * w, cy = a.y + 0.5f * h;
            float pcx = delta[0] * w + cx, pcy = delta[1] * h + cy;
            float pw = __expf(delta[2]) * w, ph = __expf(delta[3]) * h;
            float px1 = pcx - 0.5f * pw, py1 = pcy - 0.5f * ph;
            float px2 = pcx + 0.5f * pw, py2 = pcy + 0.5f * ph;

            float iw = fmaxf(fminf(px2, gx2) - fmaxf(px1, gx1), 0.f);
            float ih = fmaxf(fminf(py2, gy2) - fmaxf(py1, gy1), 0.f);
            float inter = iw * ih;
            float aa = (px2 - px1) * (py2 - py1);
            float ab = (gx2 - gx1) * (gy2 - gy1);
            float uni = aa + ab - inter;
            float iou = inter / fmaxf(uni, 1e-9f);
            float ew = fmaxf(fmaxf(px2, gx2) - fminf(px1, gx1), 0.f);
            float eh = fmaxf(fmaxf(py2, gy2) - fminf(py1, gy1), 0.f);
            float enc = ew * eh;
            float giou = iou - (enc - uni) / fmaxf(enc, 1e-9f);
            giouv = 1.f - giou;
        }
    }

    // ---- block reduction (doubles), then atomic into globals ----
    double dq = (double)qfl, dd = dflv, dg = (double)giouv;
    int pc = posf;
#pragma unroll
    for (int o = 16; o >= 1; o >>= 1) {
        dq += __shfl_down_sync(0xffffffffu, dq, o);
        dd += __shfl_down_sync(0xffffffffu, dd, o);
        dg += __shfl_down_sync(0xffffffffu, dg, o);
        pc += __shfl_down_sync(0xffffffffu, pc, o);
    }
    __shared__ double rq[TPB / 32], rd[TPB / 32], rg[TPB / 32];
    __shared__ int rc[TPB / 32];
    int wid = tid >> 5, lane = tid & 31;
    if (lane == 0) { rq[wid] = dq; rd[wid] = dd; rg[wid] = dg; rc[wid] = pc; }
    __syncthreads();
    if (tid == 0) {
        double tq = 0, td = 0, tg = 0; int tc = 0;
        for (int i = 0; i < TPB / 32; i++) { tq += rq[i]; td += rd[i]; tg += rg[i]; tc += rc[i]; }
        atomicAdd(&g_acc[0], tq);
        atomicAdd(&g_acc[1], td);
        atomicAdd(&g_acc[2], tg);
        atomicAdd(&g_poscnt, (unsigned long long)tc);
        __threadfence();
        unsigned int total = gridDim.x * gridDim.y;
        unsigned int done = atomicAdd(&g_cnt, 1u);
        if (done == total - 1) {
            double sq = atomicAdd(&g_acc[0], 0.0);
            double sd2 = atomicAdd(&g_acc[1], 0.0);
            double sg = atomicAdd(&g_acc[2], 0.0);
            unsigned long long cnt = atomicAdd(&g_poscnt, 0ull);
            double np  = (double)(cnt > 0 ? cnt : 1ull);
            double npd = (double)(cnt > 0 ? cnt * 4ull : 1ull);
            double qv = sq / np;
            double dv = sd2 / npd;
            dv = fmin(fmax(dv, 0.0), 1.0);
            double gv = sg / np;
            out[0] = (float)(qv + dv + gv);
            out[1] = (float)qv;
            out[2] = (float)dv;
            out[3] = (float)gv;
        }
    }
}

extern "C" void kernel_launch(void* const* d_in, const int* in_sizes, int n_in,
                              void* d_out, int out_size) {
    const float* cls_preds = (const float*)d_in[0];
    const float* reg_preds = (const float*)d_in[1];
    const float* anchors   = (const float*)d_in[2];
    const float* gt        = (const float*)d_in[3];
    const int*   labels    = (const int*)d_in[4];

    int N = in_sizes[2] / 4;                 // 21824
    int B = in_sizes[3] / (MGT * 4);         // 16

    thr_kernel<<<B * MGT, 32>>>(gt, B);
    mask_kernel<<<B * MGT, 32>>>(gt);
    dim3 grid((N + TPB - 1) / TPB, B);
    loss_kernel<<<grid, TPB>>>(cls_preds, reg_preds, anchors, gt, labels, N, (float*)d_out);
}